// round 12
// baseline (speedup 1.0000x reference)
#include <cuda_runtime.h>
#include <cstdint>
#include <cstddef>

// ============================================================================
// LSTM (B=8192, H=512, T=32, F=96) on sm_100 via mma.sync.m16n8k8 TF32.
//
// R12 change vs R11 (passed 4085us; step 134.8us, tensor=57.1%, issue=44.2%,
// occ=23.3%): warp-starvation fix. Warp tile 64x32 -> 32x32 (acc 32 regs,
// ~85 regs/thread), CTA M=64 x N=128 (8 warps, 2x4), stage = A 8KB + B 16KB
// = 24KB x3 = 72KB -> __launch_bounds__(256,3): 3 CTAs/SM = 24 warps
// (6/SMSP) inside both the RF (84 regs) and smem (216<=228KB) budgets.
// g_Wt layout, swizzle, k-permutation, epilogue mapping all unchanged
// (N=128 still = 4 gates x 32 units). Grid 2048 CTAs -> 4.61 waves (tail
// loss 13.5% -> 7.8%). Priced-in costs: LDS/MMA 0.375->0.5 v4, B L2
// traffic x2.
// ============================================================================

#define DEVI __device__ __forceinline__

#define BATCH   8192
#define HID     512
#define G4      2048
#define TSTEPS  32
#define INFEAT  96
#define NCHUNK  19
#define THREADS 256

#define A_BYTES   8192               // 64 rows x 128B
#define STAGE     24576              // A 8KB | B 16KB
#define SMEM_NEED (3 * STAGE)
#define SMEM_ALLOC (SMEM_NEED + 256)

#define WT_FLOATS (16 * NCHUNK * 128 * 32)   // 4.75MB pre-tiled W

// ------------------------- device scratch (no allocs) -----------------------
__device__ float g_h[2][BATCH * HID];
__device__ float g_c[BATCH * HID];
__device__ float g_bias[G4];
__device__ float g_Wt[WT_FLOATS];
__device__ float g_xT[TSTEPS * BATCH * INFEAT];

// ------------------------------ helpers -------------------------------------
DEVI uint32_t smem_u32(const void* p) {
    uint32_t a;
    asm("{ .reg .u64 t; cvta.to.shared.u64 t, %1; cvt.u32.u64 %0, t; }" : "=r"(a) : "l"(p));
    return a;
}
DEVI float to_tf32(float x) {
    uint32_t o;
    asm("cvt.rna.tf32.f32 %0, %1;" : "=r"(o) : "f"(x));
    return __uint_as_float(o);
}
DEVI float ex2f(float x) { float y; asm("ex2.approx.f32 %0, %1;" : "=f"(y) : "f"(x)); return y; }
DEVI float rcpf(float x) { float y; asm("rcp.approx.f32 %0, %1;" : "=f"(y) : "f"(x)); return y; }
DEVI float sigm(float x) { return rcpf(1.0f + ex2f(x * -1.44269504088896f)); }
DEVI float tanh_(float x) { return fmaf(2.0f, sigm(x + x), -1.0f); }

DEVI uint32_t swz(uint32_t g) { return ((g & 1u) << 2) | (g >> 1); }

DEVI void cp16(uint32_t sdst, const void* gsrc) {
    asm volatile("cp.async.cg.shared.global [%0], [%1], 16;" :: "r"(sdst), "l"(gsrc) : "memory");
}
DEVI void mma_tf32(float* c, uint32_t a0, uint32_t a1, uint32_t a2, uint32_t a3,
                   uint32_t b0, uint32_t b1) {
    asm volatile(
        "mma.sync.aligned.m16n8k8.row.col.f32.tf32.tf32.f32 "
        "{%0,%1,%2,%3}, {%4,%5,%6,%7}, {%8,%9}, {%0,%1,%2,%3};"
        : "+f"(c[0]), "+f"(c[1]), "+f"(c[2]), "+f"(c[3])
        : "r"(a0), "r"(a1), "r"(a2), "r"(a3), "r"(b0), "r"(b1));
}

// ------------------------------ prep kernels --------------------------------
__global__ void prep_x_kernel(const float* __restrict__ in) {
    int idx = blockIdx.x * blockDim.x + threadIdx.x;
    if (idx >= BATCH * 3 * 32 * 32) return;
    int w  = idx & 31;
    int t  = (idx >> 5) & 31;
    int c3 = idx >> 10;
    int ch = c3 % 3;
    int b  = c3 / 3;
    g_xT[((size_t)t * BATCH + b) * INFEAT + w * 3 + ch] = to_tf32(in[idx]);
}

__global__ void prep_misc_kernel(const float* __restrict__ h0, const float* __restrict__ c0,
                                 const float* __restrict__ bih, const float* __restrict__ bhh) {
    int i = blockIdx.x * blockDim.x + threadIdx.x;
    if (i < BATCH * HID) {
        g_h[0][i] = to_tf32(h0[i]);
        g_c[i]    = c0[i];
    }
    if (i < G4) g_bias[i] = bih[i] + bhh[i];
}

// g_Wt[(nhi*NCHUNK + kc)*4096 + r*32 + c]: row r = gate(r)*512 + nhi*32 +
// unit(r), swizzle (chunk ^= swz(r&7)) baked in. (unchanged from R9)
__global__ void prep_w_kernel(const float* __restrict__ Wih, const float* __restrict__ Whh) {
    int idx = blockIdx.x * blockDim.x + threadIdx.x;
    if (idx >= WT_FLOATS) return;
    int pos = idx & 4095;
    int kc  = (idx >> 12) % NCHUNK;
    int nhi = idx / (NCHUNK * 4096);
    int r   = pos >> 5;
    int c   = pos & 31;
    int cc_dst = c >> 2, j = c & 3;
    int cc_src = cc_dst ^ (int)swz((uint32_t)(r & 7));
    int k_local = cc_src * 4 + j;
    int wrow = ((r >> 3) & 3) * HID + nhi * 32 + ((r >> 5) << 3) + (r & 7);
    float v;
    if (kc < 16) v = Whh[(size_t)wrow * HID    + kc * 32        + k_local];
    else         v = Wih[(size_t)wrow * INFEAT + (kc - 16) * 32 + k_local];
    g_Wt[idx] = to_tf32(v);
}

// --------------------- templated loader / compute bodies --------------------
// S = pipeline stage (compile-time). AP = A source 32-row-group stride in
// floats: 16384 for h (32*512), 3072 for x (32*96).
template<int S, int AP>
DEVI void load_stage(uint32_t dstA, uint32_t dstB,
                     const float* __restrict__ srcA, const float* __restrict__ srcB) {
    #pragma unroll
    for (int u = 0; u < 2; u++)                       // A: 64 rows
        cp16(dstA + S * STAGE + u * 4096, srcA + (size_t)u * AP);
    #pragma unroll
    for (int u = 0; u < 4; u++)                       // B: 16KB linear
        cp16(dstB + S * STAGE + u * 4096, srcB + u * 1024);
    asm volatile("cp.async.commit_group;" ::: "memory");
}

template<int S>
DEVI void mma_chunk(float (&acc)[2][4][4],
                    uint32_t RA0, uint32_t RA1, uint32_t RB0, uint32_t RB1) {
    #pragma unroll
    for (int p = 0; p < 2; p++) {
        const uint32_t RA = (p ? RA1 : RA0) + S * STAGE;
        const uint32_t RB = (p ? RB1 : RB0) + S * STAGE + A_BYTES;
        uint32_t bw[4][4];
        #pragma unroll
        for (int n = 0; n < 4; n++)
            asm volatile("ld.shared.v4.u32 {%0,%1,%2,%3}, [%4];"
                         : "=r"(bw[n][0]), "=r"(bw[n][1]), "=r"(bw[n][2]), "=r"(bw[n][3])
                         : "r"(RB + n * 1024));
        #pragma unroll
        for (int m = 0; m < 2; m++) {
            uint32_t x0, x1, x2, x3, y0, y1, y2, y3;
            asm volatile("ld.shared.v4.u32 {%0,%1,%2,%3}, [%4];"
                         : "=r"(x0), "=r"(x1), "=r"(x2), "=r"(x3) : "r"(RA + m * 2048));
            asm volatile("ld.shared.v4.u32 {%0,%1,%2,%3}, [%4];"
                         : "=r"(y0), "=r"(y1), "=r"(y2), "=r"(y3) : "r"(RA + m * 2048 + 1024));
            #pragma unroll
            for (int n = 0; n < 4; n++) {
                mma_tf32(acc[m][n], x0, y0, x1, y1, bw[n][0], bw[n][1]);
                mma_tf32(acc[m][n], x2, y2, x3, y3, bw[n][2], bw[n][3]);
            }
        }
    }
}

#define WAITG(N) asm volatile("cp.async.wait_group " #N ";" ::: "memory")

// ------------------------------- step kernel --------------------------------
__global__ void __launch_bounds__(THREADS, 3) step_kernel(int t) {
    extern __shared__ char dsm[];
    uint32_t sb = smem_u32(dsm);
    sb = (sb + 127u) & ~127u;

    const int tid  = threadIdx.x;
    const int warp = tid >> 5, lane = tid & 31;
    const int wm = warp >> 2, wn = warp & 3;     // 2x4 warp grid, tile 32x32
    const int g  = lane >> 2, q = lane & 3;
    const int nhi   = blockIdx.y;
    const int nh    = nhi * 32;
    const int brow0 = blockIdx.x * 64;

    const float* __restrict__ hin  = g_h[t & 1];
    float*       __restrict__ hout = g_h[(t + 1) & 1];
    const float* __restrict__ xT   = g_xT + (size_t)t * BATCH * INFEAT;

    // persistent cp.async addressing
    const int r0 = tid >> 3, cc0 = tid & 7;      // A rows 0..31 (+u*32)
    const uint32_t dstA = sb + r0 * 128 + (((uint32_t)cc0 ^ swz((uint32_t)(r0 & 7))) << 4);
    const uint32_t dstB = sb + A_BYTES + tid * 16;
    const float* srcA  = hin + (size_t)(brow0 + r0) * HID + cc0 * 4;
    const float* srcB  = g_Wt + ((size_t)(nhi * NCHUNK) << 12) + tid * 4;
    const float* srcAx = xT + (size_t)(brow0 + r0) * INFEAT + cc0 * 4;

    // persistent fragment base registers (k-permutation chunk (4p+q)^swz(g))
    const uint32_t sg  = swz((uint32_t)g);
    const uint32_t RA0 = sb + (uint32_t)(wm * 32 + g) * 128 + (((uint32_t)q ^ sg) << 4);
    const uint32_t RA1 = sb + (uint32_t)(wm * 32 + g) * 128 + (((uint32_t)(4 + q) ^ sg) << 4);
    const uint32_t RB0 = sb + (uint32_t)(wn * 32 + g) * 128 + (((uint32_t)q ^ sg) << 4);
    const uint32_t RB1 = sb + (uint32_t)(wn * 32 + g) * 128 + (((uint32_t)(4 + q) ^ sg) << 4);

    // prologue: chunks 0, 1
    load_stage<0, 16384>(dstA, dstB, srcA,      srcB);
    load_stage<1, 16384>(dstA, dstB, srcA + 32, srcB + 4096);
    srcA += 64; srcB += 8192;

    float acc[2][4][4] = {};

    // kc = 0..11 (4 groups of 3; loads cover chunks 2..13, all h)
    for (int i = 0; i < 4; i++) {
        WAITG(1); __syncthreads();
        load_stage<2, 16384>(dstA, dstB, srcA, srcB); srcA += 32; srcB += 4096;
        mma_chunk<0>(acc, RA0, RA1, RB0, RB1);

        WAITG(1); __syncthreads();
        load_stage<0, 16384>(dstA, dstB, srcA, srcB); srcA += 32; srcB += 4096;
        mma_chunk<1>(acc, RA0, RA1, RB0, RB1);

        WAITG(1); __syncthreads();
        load_stage<1, 16384>(dstA, dstB, srcA, srcB); srcA += 32; srcB += 4096;
        mma_chunk<2>(acc, RA0, RA1, RB0, RB1);
    }

    // kc = 12 (load chunk 14, h)
    WAITG(1); __syncthreads();
    load_stage<2, 16384>(dstA, dstB, srcA, srcB); srcA += 32; srcB += 4096;
    mma_chunk<0>(acc, RA0, RA1, RB0, RB1);
    // kc = 13 (load chunk 15, h)
    WAITG(1); __syncthreads();
    load_stage<0, 16384>(dstA, dstB, srcA, srcB); srcB += 4096;
    mma_chunk<1>(acc, RA0, RA1, RB0, RB1);
    // kc = 14 (load chunk 16, x)
    WAITG(1); __syncthreads();
    load_stage<1, 3072>(dstA, dstB, srcAx, srcB); srcB += 4096;
    mma_chunk<2>(acc, RA0, RA1, RB0, RB1);
    // kc = 15 (load chunk 17, x)
    WAITG(1); __syncthreads();
    load_stage<2, 3072>(dstA, dstB, srcAx + 32, srcB); srcB += 4096;
    mma_chunk<0>(acc, RA0, RA1, RB0, RB1);
    // kc = 16 (load chunk 18, x)
    WAITG(1); __syncthreads();
    load_stage<0, 3072>(dstA, dstB, srcAx + 64, srcB);
    mma_chunk<1>(acc, RA0, RA1, RB0, RB1);
    // kc = 17
    WAITG(1); __syncthreads();
    mma_chunk<2>(acc, RA0, RA1, RB0, RB1);
    // kc = 18
    WAITG(0); __syncthreads();
    mma_chunk<0>(acc, RA0, RA1, RB0, RB1);

    // -------------------- in-register LSTM epilogue -------------------------
    // acc[m][n][slot]: rows wm*32+m*16+g(+8), gate n, units u0..u0+1.
    const int u0 = nh + wn * 8 + 2 * q;
    const float2 bi = *(const float2*)(g_bias + 0 * HID + u0);
    const float2 bf = *(const float2*)(g_bias + 1 * HID + u0);
    const float2 bg = *(const float2*)(g_bias + 2 * HID + u0);
    const float2 bo = *(const float2*)(g_bias + 3 * HID + u0);

    #pragma unroll
    for (int m = 0; m < 2; m++) {
        #pragma unroll
        for (int rh = 0; rh < 2; rh++) {
            const int row = brow0 + wm * 32 + m * 16 + g + rh * 8;
            const int s0 = rh * 2;
            float* cptr = g_c  + (size_t)row * HID + u0;
            float* hptr = hout + (size_t)row * HID + u0;
            float2 cv = *(const float2*)(cptr);

            float i0 = sigm (acc[m][0][s0]     + bi.x);
            float f0 = sigm (acc[m][1][s0]     + bf.x);
            float g0 = tanh_(acc[m][2][s0]     + bg.x);
            float o0 = sigm (acc[m][3][s0]     + bo.x);
            float i1 = sigm (acc[m][0][s0 + 1] + bi.y);
            float f1 = sigm (acc[m][1][s0 + 1] + bf.y);
            float g1 = tanh_(acc[m][2][s0 + 1] + bg.y);
            float o1 = sigm (acc[m][3][s0 + 1] + bo.y);

            float cn0 = fmaf(f0, cv.x, i0 * g0);
            float cn1 = fmaf(f1, cv.y, i1 * g1);
            *(float2*)(cptr) = make_float2(cn0, cn1);
            *(float2*)(hptr) = make_float2(to_tf32(o0 * tanh_(cn0)),
                                           to_tf32(o1 * tanh_(cn1)));
        }
    }
}

// ------------------------------- final kernel -------------------------------
__global__ void final_kernel(const float* __restrict__ Wout, const float* __restrict__ bout,
                             float* __restrict__ out) {
    int idx = blockIdx.x * blockDim.x + threadIdx.x;
    if (idx >= BATCH * 10) return;
    int b = idx / 10, cls = idx % 10;
    const float* h  = g_h[0] + (size_t)b * HID;        // step 31 wrote g_h[0]
    const float* wv = Wout + (size_t)cls * HID;
    float acc = 0.f;
    #pragma unroll 4
    for (int i = 0; i < HID; i += 4) {
        float4 hv = *(const float4*)(h + i);
        float4 wf = *(const float4*)(wv + i);
        acc = fmaf(hv.x, wf.x, acc);
        acc = fmaf(hv.y, wf.y, acc);
        acc = fmaf(hv.z, wf.z, acc);
        acc = fmaf(hv.w, wf.w, acc);
    }
    out[idx] = acc + bout[cls];
}

// --------------------------------- launch -----------------------------------
extern "C" void kernel_launch(void* const* d_in, const int* in_sizes, int n_in,
                              void* d_out, int out_size) {
    const float* inputs = (const float*)d_in[0];
    const float* h0     = (const float*)d_in[1];
    const float* c0     = (const float*)d_in[2];
    const float* W_ih   = (const float*)d_in[3];
    const float* W_hh   = (const float*)d_in[4];
    const float* b_ih   = (const float*)d_in[5];
    const float* b_hh   = (const float*)d_in[6];
    const float* W_out  = (const float*)d_in[7];
    const float* b_out  = (const float*)d_in[8];
    float* out = (float*)d_out;
    (void)in_sizes; (void)n_in; (void)out_size;

    cudaFuncSetAttribute(step_kernel, cudaFuncAttributeMaxDynamicSharedMemorySize, SMEM_ALLOC);

    prep_x_kernel<<<(BATCH * 3 * 32 * 32 + 255) / 256, 256>>>(inputs);
    prep_misc_kernel<<<(BATCH * HID + 255) / 256, 256>>>(h0, c0, b_ih, b_hh);
    prep_w_kernel<<<(WT_FLOATS + 255) / 256, 256>>>(W_ih, W_hh);

    dim3 grid(BATCH / 64, HID / 32);   // (128, 16) = 2048 CTAs
    for (int t = 0; t < TSTEPS; t++)
        step_kernel<<<grid, THREADS, SMEM_ALLOC>>>(t);

    final_kernel<<<(BATCH * 10 + 255) / 256, 256>>>(W_out, b_out, out);
}

// round 13
// speedup vs baseline: 1.1310x; 1.1310x over previous
#include <cuda_runtime.h>
#include <cstdint>
#include <cstddef>

// ============================================================================
// LSTM (B=8192, H=512, T=32, F=96) on sm_100 via mma.sync.m16n8k8 TF32.
//
// R13 = R11 tiling (64x32 warp tile, CTA 128x128, 2 CTAs/SM -- best measured;
// R12's 32x32/3-CTA experiment REGRESSED: instruction stream per FLOP grew
// faster than issue rate) + accumulator-RAW fix: mma_chunk now issues all
// four n-MMAs at kb=2p before the four at kb=2p+1, so same-accumulator
// reuse distance rises 1 -> 4 MMAs (was back-to-back, serializing on MMA
// latency instead of pipe throughput). Zero register cost; per-accumulator
// k-order unchanged -> bit-identical math.
// ============================================================================

#define DEVI __device__ __forceinline__

#define BATCH   8192
#define HID     512
#define G4      2048
#define TSTEPS  32
#define INFEAT  96
#define NCHUNK  19
#define THREADS 256

#define STAGE     32768              // A 16KB | B 16KB
#define SMEM_NEED (3 * STAGE)
#define SMEM_ALLOC (SMEM_NEED + 256)

#define WT_FLOATS (16 * NCHUNK * 128 * 32)   // 4.75MB pre-tiled W

// ------------------------- device scratch (no allocs) -----------------------
__device__ float g_h[2][BATCH * HID];
__device__ float g_c[BATCH * HID];
__device__ float g_bias[G4];
__device__ float g_Wt[WT_FLOATS];
__device__ float g_xT[TSTEPS * BATCH * INFEAT];

// ------------------------------ helpers -------------------------------------
DEVI uint32_t smem_u32(const void* p) {
    uint32_t a;
    asm("{ .reg .u64 t; cvta.to.shared.u64 t, %1; cvt.u32.u64 %0, t; }" : "=r"(a) : "l"(p));
    return a;
}
DEVI float to_tf32(float x) {
    uint32_t o;
    asm("cvt.rna.tf32.f32 %0, %1;" : "=r"(o) : "f"(x));
    return __uint_as_float(o);
}
DEVI float ex2f(float x) { float y; asm("ex2.approx.f32 %0, %1;" : "=f"(y) : "f"(x)); return y; }
DEVI float rcpf(float x) { float y; asm("rcp.approx.f32 %0, %1;" : "=f"(y) : "f"(x)); return y; }
DEVI float sigm(float x) { return rcpf(1.0f + ex2f(x * -1.44269504088896f)); }
DEVI float tanh_(float x) { return fmaf(2.0f, sigm(x + x), -1.0f); }

DEVI uint32_t swz(uint32_t g) { return ((g & 1u) << 2) | (g >> 1); }

DEVI void cp16(uint32_t sdst, const void* gsrc) {
    asm volatile("cp.async.cg.shared.global [%0], [%1], 16;" :: "r"(sdst), "l"(gsrc) : "memory");
}
DEVI void mma_tf32(float* c, uint32_t a0, uint32_t a1, uint32_t a2, uint32_t a3,
                   uint32_t b0, uint32_t b1) {
    asm volatile(
        "mma.sync.aligned.m16n8k8.row.col.f32.tf32.tf32.f32 "
        "{%0,%1,%2,%3}, {%4,%5,%6,%7}, {%8,%9}, {%0,%1,%2,%3};"
        : "+f"(c[0]), "+f"(c[1]), "+f"(c[2]), "+f"(c[3])
        : "r"(a0), "r"(a1), "r"(a2), "r"(a3), "r"(b0), "r"(b1));
}

// ------------------------------ prep kernels --------------------------------
__global__ void prep_x_kernel(const float* __restrict__ in) {
    int idx = blockIdx.x * blockDim.x + threadIdx.x;
    if (idx >= BATCH * 3 * 32 * 32) return;
    int w  = idx & 31;
    int t  = (idx >> 5) & 31;
    int c3 = idx >> 10;
    int ch = c3 % 3;
    int b  = c3 / 3;
    g_xT[((size_t)t * BATCH + b) * INFEAT + w * 3 + ch] = to_tf32(in[idx]);
}

__global__ void prep_misc_kernel(const float* __restrict__ h0, const float* __restrict__ c0,
                                 const float* __restrict__ bih, const float* __restrict__ bhh) {
    int i = blockIdx.x * blockDim.x + threadIdx.x;
    if (i < BATCH * HID) {
        g_h[0][i] = to_tf32(h0[i]);
        g_c[i]    = c0[i];
    }
    if (i < G4) g_bias[i] = bih[i] + bhh[i];
}

// g_Wt[(nhi*NCHUNK + kc)*4096 + r*32 + c]: row r = gate(r)*512 + nhi*32 +
// unit(r), swizzle (chunk ^= swz(r&7)) baked in.
__global__ void prep_w_kernel(const float* __restrict__ Wih, const float* __restrict__ Whh) {
    int idx = blockIdx.x * blockDim.x + threadIdx.x;
    if (idx >= WT_FLOATS) return;
    int pos = idx & 4095;
    int kc  = (idx >> 12) % NCHUNK;
    int nhi = idx / (NCHUNK * 4096);
    int r   = pos >> 5;
    int c   = pos & 31;
    int cc_dst = c >> 2, j = c & 3;
    int cc_src = cc_dst ^ (int)swz((uint32_t)(r & 7));
    int k_local = cc_src * 4 + j;
    int wrow = ((r >> 3) & 3) * HID + nhi * 32 + ((r >> 5) << 3) + (r & 7);
    float v;
    if (kc < 16) v = Whh[(size_t)wrow * HID    + kc * 32        + k_local];
    else         v = Wih[(size_t)wrow * INFEAT + (kc - 16) * 32 + k_local];
    g_Wt[idx] = to_tf32(v);
}

// --------------------- templated loader / compute bodies --------------------
// S = pipeline stage (compile-time). AP = A source 32-row-group stride in
// floats: 16384 for h, 3072 for x.
template<int S, int AP>
DEVI void load_stage(uint32_t dstA, uint32_t dstB,
                     const float* __restrict__ srcA, const float* __restrict__ srcB) {
    #pragma unroll
    for (int u = 0; u < 4; u++)
        cp16(dstA + S * STAGE + u * 4096, srcA + (size_t)u * AP);
    #pragma unroll
    for (int u = 0; u < 4; u++)
        cp16(dstB + S * STAGE + u * 4096, srcB + u * 1024);
    asm volatile("cp.async.commit_group;" ::: "memory");
}

template<int S>
DEVI void mma_chunk(float (&acc)[4][4][4],
                    uint32_t RA0, uint32_t RA1, uint32_t RB0, uint32_t RB1) {
    #pragma unroll
    for (int p = 0; p < 2; p++) {
        const uint32_t RA = (p ? RA1 : RA0) + S * STAGE;
        const uint32_t RB = (p ? RB1 : RB0) + S * STAGE + 16384;
        uint32_t bw[4][4];
        #pragma unroll
        for (int n = 0; n < 4; n++)
            asm volatile("ld.shared.v4.u32 {%0,%1,%2,%3}, [%4];"
                         : "=r"(bw[n][0]), "=r"(bw[n][1]), "=r"(bw[n][2]), "=r"(bw[n][3])
                         : "r"(RB + n * 1024));
        #pragma unroll
        for (int m = 0; m < 4; m++) {
            uint32_t x0, x1, x2, x3, y0, y1, y2, y3;
            asm volatile("ld.shared.v4.u32 {%0,%1,%2,%3}, [%4];"
                         : "=r"(x0), "=r"(x1), "=r"(x2), "=r"(x3) : "r"(RA + m * 2048));
            asm volatile("ld.shared.v4.u32 {%0,%1,%2,%3}, [%4];"
                         : "=r"(y0), "=r"(y1), "=r"(y2), "=r"(y3) : "r"(RA + m * 2048 + 1024));
            // RAW fix: all n at kb=2p first, then all n at kb=2p+1 --
            // same-accumulator reuse distance 1 -> 4 MMAs.
            #pragma unroll
            for (int n = 0; n < 4; n++)
                mma_tf32(acc[m][n], x0, y0, x1, y1, bw[n][0], bw[n][1]);  // kb = 2p
            #pragma unroll
            for (int n = 0; n < 4; n++)
                mma_tf32(acc[m][n], x2, y2, x3, y3, bw[n][2], bw[n][3]);  // kb = 2p+1
        }
    }
}

#define WAITG(N) asm volatile("cp.async.wait_group " #N ";" ::: "memory")

// ------------------------------- step kernel --------------------------------
__global__ void __launch_bounds__(THREADS, 2) step_kernel(int t) {
    extern __shared__ char dsm[];
    uint32_t sb = smem_u32(dsm);
    sb = (sb + 127u) & ~127u;

    const int tid  = threadIdx.x;
    const int warp = tid >> 5, lane = tid & 31;
    const int wm = warp >> 2, wn = warp & 3;
    const int g  = lane >> 2, q = lane & 3;
    const int nhi   = blockIdx.y;
    const int nh    = nhi * 32;
    const int brow0 = blockIdx.x * 128;

    const float* __restrict__ hin  = g_h[t & 1];
    float*       __restrict__ hout = g_h[(t + 1) & 1];
    const float* __restrict__ xT   = g_xT + (size_t)t * BATCH * INFEAT;

    // persistent cp.async addressing
    const int r0 = tid >> 3, cc0 = tid & 7;
    const uint32_t dstA = sb + r0 * 128 + (((uint32_t)cc0 ^ swz((uint32_t)(r0 & 7))) << 4);
    const uint32_t dstB = sb + 16384 + tid * 16;
    const float* srcA  = hin + (size_t)(brow0 + r0) * HID + cc0 * 4;
    const float* srcB  = g_Wt + ((size_t)(nhi * NCHUNK) << 12) + tid * 4;
    const float* srcAx = xT + (size_t)(brow0 + r0) * INFEAT + cc0 * 4;

    // persistent fragment base registers (k-permutation chunk (4p+q)^swz(g))
    const uint32_t sg  = swz((uint32_t)g);
    const uint32_t RA0 = sb + (uint32_t)(wm * 64 + g) * 128 + (((uint32_t)q ^ sg) << 4);
    const uint32_t RA1 = sb + (uint32_t)(wm * 64 + g) * 128 + (((uint32_t)(4 + q) ^ sg) << 4);
    const uint32_t RB0 = sb + (uint32_t)(wn * 32 + g) * 128 + (((uint32_t)q ^ sg) << 4);
    const uint32_t RB1 = sb + (uint32_t)(wn * 32 + g) * 128 + (((uint32_t)(4 + q) ^ sg) << 4);

    // prologue: chunks 0, 1
    load_stage<0, 16384>(dstA, dstB, srcA,      srcB);
    load_stage<1, 16384>(dstA, dstB, srcA + 32, srcB + 4096);
    srcA += 64; srcB += 8192;

    float acc[4][4][4] = {};

    // kc = 0..11 (4 groups of 3; loads cover chunks 2..13, all h)
    for (int i = 0; i < 4; i++) {
        WAITG(1); __syncthreads();
        load_stage<2, 16384>(dstA, dstB, srcA, srcB); srcA += 32; srcB += 4096;
        mma_chunk<0>(acc, RA0, RA1, RB0, RB1);

        WAITG(1); __syncthreads();
        load_stage<0, 16384>(dstA, dstB, srcA, srcB); srcA += 32; srcB += 4096;
        mma_chunk<1>(acc, RA0, RA1, RB0, RB1);

        WAITG(1); __syncthreads();
        load_stage<1, 16384>(dstA, dstB, srcA, srcB); srcA += 32; srcB += 4096;
        mma_chunk<2>(acc, RA0, RA1, RB0, RB1);
    }

    // kc = 12 (load chunk 14, h)
    WAITG(1); __syncthreads();
    load_stage<2, 16384>(dstA, dstB, srcA, srcB); srcA += 32; srcB += 4096;
    mma_chunk<0>(acc, RA0, RA1, RB0, RB1);
    // kc = 13 (load chunk 15, h)
    WAITG(1); __syncthreads();
    load_stage<0, 16384>(dstA, dstB, srcA, srcB); srcB += 4096;
    mma_chunk<1>(acc, RA0, RA1, RB0, RB1);
    // kc = 14 (load chunk 16, x)
    WAITG(1); __syncthreads();
    load_stage<1, 3072>(dstA, dstB, srcAx, srcB); srcB += 4096;
    mma_chunk<2>(acc, RA0, RA1, RB0, RB1);
    // kc = 15 (load chunk 17, x)
    WAITG(1); __syncthreads();
    load_stage<2, 3072>(dstA, dstB, srcAx + 32, srcB); srcB += 4096;
    mma_chunk<0>(acc, RA0, RA1, RB0, RB1);
    // kc = 16 (load chunk 18, x)
    WAITG(1); __syncthreads();
    load_stage<0, 3072>(dstA, dstB, srcAx + 64, srcB);
    mma_chunk<1>(acc, RA0, RA1, RB0, RB1);
    // kc = 17
    WAITG(1); __syncthreads();
    mma_chunk<2>(acc, RA0, RA1, RB0, RB1);
    // kc = 18
    WAITG(0); __syncthreads();
    mma_chunk<0>(acc, RA0, RA1, RB0, RB1);

    // -------------------- in-register LSTM epilogue -------------------------
    const int u0 = nh + wn * 8 + 2 * q;
    const float2 bi = *(const float2*)(g_bias + 0 * HID + u0);
    const float2 bf = *(const float2*)(g_bias + 1 * HID + u0);
    const float2 bg = *(const float2*)(g_bias + 2 * HID + u0);
    const float2 bo = *(const float2*)(g_bias + 3 * HID + u0);

    #pragma unroll
    for (int m = 0; m < 4; m++) {
        #pragma unroll
        for (int rh = 0; rh < 2; rh++) {
            const int row = brow0 + wm * 64 + m * 16 + g + rh * 8;
            const int s0 = rh * 2;
            float* cptr = g_c  + (size_t)row * HID + u0;
            float* hptr = hout + (size_t)row * HID + u0;
            float2 cv = *(const float2*)(cptr);

            float i0 = sigm (acc[m][0][s0]     + bi.x);
            float f0 = sigm (acc[m][1][s0]     + bf.x);
            float g0 = tanh_(acc[m][2][s0]     + bg.x);
            float o0 = sigm (acc[m][3][s0]     + bo.x);
            float i1 = sigm (acc[m][0][s0 + 1] + bi.y);
            float f1 = sigm (acc[m][1][s0 + 1] + bf.y);
            float g1 = tanh_(acc[m][2][s0 + 1] + bg.y);
            float o1 = sigm (acc[m][3][s0 + 1] + bo.y);

            float cn0 = fmaf(f0, cv.x, i0 * g0);
            float cn1 = fmaf(f1, cv.y, i1 * g1);
            *(float2*)(cptr) = make_float2(cn0, cn1);
            *(float2*)(hptr) = make_float2(to_tf32(o0 * tanh_(cn0)),
                                           to_tf32(o1 * tanh_(cn1)));
        }
    }
}

// ------------------------------- final kernel -------------------------------
__global__ void final_kernel(const float* __restrict__ Wout, const float* __restrict__ bout,
                             float* __restrict__ out) {
    int idx = blockIdx.x * blockDim.x + threadIdx.x;
    if (idx >= BATCH * 10) return;
    int b = idx / 10, cls = idx % 10;
    const float* h  = g_h[0] + (size_t)b * HID;        // step 31 wrote g_h[0]
    const float* wv = Wout + (size_t)cls * HID;
    float acc = 0.f;
    #pragma unroll 4
    for (int i = 0; i < HID; i += 4) {
        float4 hv = *(const float4*)(h + i);
        float4 wf = *(const float4*)(wv + i);
        acc = fmaf(hv.x, wf.x, acc);
        acc = fmaf(hv.y, wf.y, acc);
        acc = fmaf(hv.z, wf.z, acc);
        acc = fmaf(hv.w, wf.w, acc);
    }
    out[idx] = acc + bout[cls];
}

// --------------------------------- launch -----------------------------------
extern "C" void kernel_launch(void* const* d_in, const int* in_sizes, int n_in,
                              void* d_out, int out_size) {
    const float* inputs = (const float*)d_in[0];
    const float* h0     = (const float*)d_in[1];
    const float* c0     = (const float*)d_in[2];
    const float* W_ih   = (const float*)d_in[3];
    const float* W_hh   = (const float*)d_in[4];
    const float* b_ih   = (const float*)d_in[5];
    const float* b_hh   = (const float*)d_in[6];
    const float* W_out  = (const float*)d_in[7];
    const float* b_out  = (const float*)d_in[8];
    float* out = (float*)d_out;
    (void)in_sizes; (void)n_in; (void)out_size;

    cudaFuncSetAttribute(step_kernel, cudaFuncAttributeMaxDynamicSharedMemorySize, SMEM_ALLOC);

    prep_x_kernel<<<(BATCH * 3 * 32 * 32 + 255) / 256, 256>>>(inputs);
    prep_misc_kernel<<<(BATCH * HID + 255) / 256, 256>>>(h0, c0, b_ih, b_hh);
    prep_w_kernel<<<(WT_FLOATS + 255) / 256, 256>>>(W_ih, W_hh);

    dim3 grid(BATCH / 128, HID / 32);   // (64, 16) = 1024 CTAs
    for (int t = 0; t < TSTEPS; t++)
        step_kernel<<<grid, THREADS, SMEM_ALLOC>>>(t);

    final_kernel<<<(BATCH * 10 + 255) / 256, 256>>>(W_out, b_out, out);
}